// round 9
// baseline (speedup 1.0000x reference)
#include <cuda_runtime.h>
#include <cstdint>

// Problem constants (fixed by the dataset)
#define NMAX    500000
#define EMAX    2000000
#define EMB     32
#define IN_DIM  65
#define TB      256
#define STRIDE  32            // ELL width == warp size; P(indegree > 32) ~ 1e-15 here
#define OVFCAP  8192

// Scratch (allocation-free rule: __device__ globals)
__device__ int g_novf;
__device__ __align__(128) int  g_cnt[NMAX];              // indegree (excl. self-loop)
__device__ __align__(128) int  g_ell[(size_t)NMAX * STRIDE]; // ELL: src ids
__device__ __align__(128) int2 g_ovf[OVFCAP];            // overflow {dst, src}
__device__ __align__(128) int2 g_packed[NMAX];           // {dinv bits, x}

// ---------------------------------------------------------------------------
// K1: zero counts + overflow, out[g] = b_out[0]
// ---------------------------------------------------------------------------
__global__ void k_init(float* __restrict__ out, const float* __restrict__ b_out,
                       int N, int G) {
    int i = blockIdx.x * blockDim.x + threadIdx.x;
    if (i < N) g_cnt[i] = 0;
    if (i < G) out[i] = b_out[0];
    if (i == 0) g_novf = 0;
}

// ---------------------------------------------------------------------------
// K2: ONE pass over edges: count indegree AND scatter src into ELL slot.
// ---------------------------------------------------------------------------
__device__ __forceinline__ void fill_one(int d, int s) {
    int r = atomicAdd(&g_cnt[d], 1);
    if (r < STRIDE) {
        g_ell[(size_t)d * STRIDE + r] = s;
    } else {
        int o = atomicAdd(&g_novf, 1);
        if (o < OVFCAP) g_ovf[o] = make_int2(d, s);
    }
}

__global__ void k_degfill(const int* __restrict__ src, const int* __restrict__ dst,
                          int E) {
    int t = blockIdx.x * blockDim.x + threadIdx.x;
    int e = t * 4;
    if (e + 3 < E) {
        int4 d4 = *reinterpret_cast<const int4*>(dst + e);
        int4 s4 = *reinterpret_cast<const int4*>(src + e);
        fill_one(d4.x, s4.x);
        fill_one(d4.y, s4.y);
        fill_one(d4.z, s4.z);
        fill_one(d4.w, s4.w);
    } else {
        for (int k = e; k < E; k++) fill_one(dst[k], src[k]);
    }
}

// ---------------------------------------------------------------------------
// K3: packed[i] = {rsqrt(1+cnt[i]), x[i]}
// ---------------------------------------------------------------------------
__global__ void k_pack(const int* __restrict__ x, int N) {
    int i = blockIdx.x * blockDim.x + threadIdx.x;
    if (i < N)
        g_packed[i] = make_int2(__float_as_int(rsqrtf(1.0f + (float)g_cnt[i])), x[i]);
}

// ---------------------------------------------------------------------------
// K4: WARP-PER-NODE, lane = EMB column.
//     Lane-parallel prefetch of all <=32 edge payloads (full MLP),
//     then a memory-free shuffle+LDS+FFMA mainloop. Conflict-free LDS.
// ---------------------------------------------------------------------------
__device__ __forceinline__ float tanha(float v) {
    float r;
    asm("tanh.approx.f32 %0, %1;" : "=f"(r) : "f"(v));
    return r;
}

#define WPITCH 33   // bank = (x + lane) mod 32 -> conflict-free per LDS

__global__ void __launch_bounds__(TB)
k_aggpool(const int* __restrict__ batch,
          const float* __restrict__ W,
          const float* __restrict__ b_conv,
          const float* __restrict__ W_out,
          float* __restrict__ out, int N) {
    __shared__ float sW[IN_DIM * WPITCH];
    __shared__ float sb[EMB];
    __shared__ float so[EMB];
    for (int t = threadIdx.x; t < IN_DIM * EMB; t += blockDim.x) {
        int r = t / EMB, cc = t % EMB;
        sW[r * WPITCH + cc] = W[t];
    }
    if (threadIdx.x < EMB) {
        sb[threadIdx.x] = b_conv[threadIdx.x];
        so[threadIdx.x] = W_out[threadIdx.x];
    }
    __syncthreads();

    int lane = threadIdx.x & 31;
    int node = blockIdx.x * (TB / 32) + (threadIdx.x >> 5);
    if (node >= N) return;

    int2 pme  = g_packed[node];      // broadcast
    float dinv = __int_as_float(pme.x);
    int   xi   = pme.y;
    int   cnt  = g_cnt[node];        // broadcast
    int   m    = cnt <= STRIDE ? cnt : STRIDE;

    // Lane-parallel prefetch: lane k holds edge k's payload {dinv_s, x_s}.
    float dv_l = 0.f;
    int   xs_l = 0;
    if (lane < m) {
        int s = g_ell[(size_t)node * STRIDE + lane];   // coalesced valid slots
        int2 ps = g_packed[s];                          // up to 32 gathers, 1 instr
        dv_l = __int_as_float(ps.x);
        xs_l = ps.y;
    }

    // acc for column `lane`: self term then shuffle mainloop (no memory deps).
    float acc = dinv * sW[xi * WPITCH + lane];
    for (int k = 0; k < m; k++) {
        float ds = __shfl_sync(0xffffffffu, dv_l, k);
        int   xs = __shfl_sync(0xffffffffu, xs_l, k);
        acc += ds * sW[xs * WPITCH + lane];
    }

    // Heavy-node path (never taken on this input; correctness fallback).
    if (cnt > STRIDE) {
        int novf = g_novf;
        if (novf > OVFCAP) novf = OVFCAP;
        for (int j = 0; j < novf; j++) {
            int2 ov = g_ovf[j];
            if (ov.x == node) {
                int2 ps = g_packed[ov.y];
                acc += __int_as_float(ps.x) * sW[ps.y * WPITCH + lane];
            }
        }
    }

    float res = tanha(acc * dinv + sb[lane]) * so[lane];
    res += __shfl_xor_sync(0xffffffffu, res, 16);
    res += __shfl_xor_sync(0xffffffffu, res, 8);
    res += __shfl_xor_sync(0xffffffffu, res, 4);
    res += __shfl_xor_sync(0xffffffffu, res, 2);
    res += __shfl_xor_sync(0xffffffffu, res, 1);
    if (lane == 0) atomicAdd(&out[batch[node]], res);
}

// ---------------------------------------------------------------------------
// Launch
// Inputs: 0:x[N] i32, 1:edge_index[2E] i32, 2:batch[N] i32,
//         3:W[65*32] f32, 4:b_conv[32] f32, 5:W_out[32] f32, 6:b_out[1] f32
// Output: out[G] f32
// ---------------------------------------------------------------------------
extern "C" void kernel_launch(void* const* d_in, const int* in_sizes, int n_in,
                              void* d_out, int out_size) {
    const int*   x     = (const int*)d_in[0];
    const int*   eidx  = (const int*)d_in[1];
    const int*   batch = (const int*)d_in[2];
    const float* W     = (const float*)d_in[3];
    const float* bconv = (const float*)d_in[4];
    const float* Wout  = (const float*)d_in[5];
    const float* bout  = (const float*)d_in[6];
    float* out = (float*)d_out;

    int N = in_sizes[0];
    int E = in_sizes[1] / 2;
    int G = out_size;

    const int* src = eidx;
    const int* dst = eidx + E;

    int initN = N > G ? N : G;
    int nbE4  = ((E + 3) / 4 + TB - 1) / TB;
    int nbN   = (N + TB - 1) / TB;
    int wpb   = TB / 32;
    int nbW   = (N + wpb - 1) / wpb;     // warp-per-node grid

    k_init   <<<(initN + TB - 1) / TB, TB>>>(out, bout, N, G);
    k_degfill<<<nbE4, TB>>>(src, dst, E);
    k_pack   <<<nbN, TB>>>(x, N);
    k_aggpool<<<nbW, TB>>>(batch, W, bconv, Wout, out, N);
}

// round 12
// speedup vs baseline: 2.1117x; 2.1117x over previous
#include <cuda_runtime.h>
#include <cstdint>

// Problem constants (fixed by the dataset)
#define NMAX    500000
#define EMAX    2000000
#define EMB     32
#define IN_DIM  65
#define TB      256
#define STRIDE  32            // ELL width; P(indegree > 32) ~ 1e-15 for this input
#define OVFCAP  8192

// Scratch (allocation-free rule: __device__ globals)
__device__ int g_novf;
__device__ __align__(128) int  g_cnt[NMAX];              // indegree (excl. self-loop)
__device__ __align__(128) int  g_ell[(size_t)NMAX * STRIDE]; // ELL: src ids
__device__ __align__(128) int2 g_ovf[OVFCAP];            // overflow {dst, src}
__device__ __align__(128) int2 g_packed[NMAX];           // {dinv bits, x}

// ---------------------------------------------------------------------------
// K1: zero counts + overflow, out[g] = b_out[0]
// ---------------------------------------------------------------------------
__global__ void k_init(float* __restrict__ out, const float* __restrict__ b_out,
                       int N, int G) {
    int i = blockIdx.x * blockDim.x + threadIdx.x;
    if (i < N) g_cnt[i] = 0;
    if (i < G) out[i] = b_out[0];
    if (i == 0) g_novf = 0;
}

// ---------------------------------------------------------------------------
// K2: ONE pass over edges: count indegree AND scatter src into ELL slot.
// ---------------------------------------------------------------------------
__device__ __forceinline__ void fill_one(int d, int s) {
    int r = atomicAdd(&g_cnt[d], 1);
    if (r < STRIDE) {
        g_ell[(size_t)d * STRIDE + r] = s;
    } else {
        int o = atomicAdd(&g_novf, 1);
        if (o < OVFCAP) g_ovf[o] = make_int2(d, s);
    }
}

__global__ void k_degfill(const int* __restrict__ src, const int* __restrict__ dst,
                          int E) {
    int t = blockIdx.x * blockDim.x + threadIdx.x;
    int e = t * 4;
    if (e + 3 < E) {
        int4 d4 = *reinterpret_cast<const int4*>(dst + e);
        int4 s4 = *reinterpret_cast<const int4*>(src + e);
        fill_one(d4.x, s4.x);
        fill_one(d4.y, s4.y);
        fill_one(d4.z, s4.z);
        fill_one(d4.w, s4.w);
    } else {
        for (int k = e; k < E; k++) fill_one(dst[k], src[k]);
    }
}

// ---------------------------------------------------------------------------
// K3: packed[i] = {rsqrt(1+cnt[i]), x[i]}
// ---------------------------------------------------------------------------
__global__ void k_pack(const int* __restrict__ x, int N) {
    int i = blockIdx.x * blockDim.x + threadIdx.x;
    if (i < N)
        g_packed[i] = make_int2(__float_as_int(rsqrtf(1.0f + (float)g_cnt[i])), x[i]);
}

// ---------------------------------------------------------------------------
// K4: 4 lanes per node, 8 EMB-columns per lane, W rows as float4 (LDS.128).
//     WPITCH4 = 9 float4 = 36 floats -> rows 16B-aligned, good quad spread.
// ---------------------------------------------------------------------------
__device__ __forceinline__ float tanha(float v) {
    float r;
    asm("tanh.approx.f32 %0, %1;" : "=f"(r) : "f"(v));
    return r;
}

#define WPITCH4 9   // float4 pitch per W row (36 floats)

__global__ void __launch_bounds__(TB)
k_aggpool(const int* __restrict__ batch,
          const float* __restrict__ W,
          const float* __restrict__ b_conv,
          const float* __restrict__ W_out,
          float* __restrict__ out, int N) {
    __shared__ float4 sW4[IN_DIM * WPITCH4];
    __shared__ float sb[EMB];
    __shared__ float so[EMB];
    {
        float* sWf = reinterpret_cast<float*>(sW4);
        for (int t = threadIdx.x; t < IN_DIM * EMB; t += blockDim.x) {
            int r = t / EMB, cc = t % EMB;
            sWf[r * (WPITCH4 * 4) + cc] = W[t];
        }
    }
    if (threadIdx.x < EMB) {
        sb[threadIdx.x] = b_conv[threadIdx.x];
        so[threadIdx.x] = W_out[threadIdx.x];
    }
    __syncthreads();

    int t    = blockIdx.x * TB + threadIdx.x;
    int node = t >> 2;          // 4 lanes per node
    int sub  = t & 3;           // column group: columns [8*sub, 8*sub+8)
    if (node >= N) return;

    int2 p = g_packed[node];    // broadcast across the 4 lanes
    float dinv = __int_as_float(p.x);
    int   xi   = p.y;
    int   cnt  = g_cnt[node];
    int   f0   = sub * 2;       // float4 index of this lane's first quad
    const int* row_ell = g_ell + (size_t)node * STRIDE;

    float4 acc0, acc1;
    {
        const float4* row = &sW4[xi * WPITCH4 + f0];
        float4 w0 = row[0], w1 = row[1];
        acc0 = make_float4(dinv * w0.x, dinv * w0.y, dinv * w0.z, dinv * w0.w);
        acc1 = make_float4(dinv * w1.x, dinv * w1.y, dinv * w1.z, dinv * w1.w);
    }

    int m = cnt <= STRIDE ? cnt : STRIDE;
    int k = 0;
    for (; k + 1 < m; k += 2) {            // 2-edge unroll for MLP
        int s0 = row_ell[k];
        int s1 = row_ell[k + 1];
        int2 p0 = g_packed[s0];
        int2 p1 = g_packed[s1];
        float d0 = __int_as_float(p0.x);
        float d1 = __int_as_float(p1.x);
        const float4* r0 = &sW4[p0.y * WPITCH4 + f0];
        const float4* r1 = &sW4[p1.y * WPITCH4 + f0];
        float4 a0 = r0[0], a1 = r0[1];
        float4 b0 = r1[0], b1 = r1[1];
        acc0.x += d0 * a0.x; acc0.y += d0 * a0.y; acc0.z += d0 * a0.z; acc0.w += d0 * a0.w;
        acc1.x += d0 * a1.x; acc1.y += d0 * a1.y; acc1.z += d0 * a1.z; acc1.w += d0 * a1.w;
        acc0.x += d1 * b0.x; acc0.y += d1 * b0.y; acc0.z += d1 * b0.z; acc0.w += d1 * b0.w;
        acc1.x += d1 * b1.x; acc1.y += d1 * b1.y; acc1.z += d1 * b1.z; acc1.w += d1 * b1.w;
    }
    if (k < m) {
        int s0 = row_ell[k];
        int2 p0 = g_packed[s0];
        float d0 = __int_as_float(p0.x);
        const float4* r0 = &sW4[p0.y * WPITCH4 + f0];
        float4 a0 = r0[0], a1 = r0[1];
        acc0.x += d0 * a0.x; acc0.y += d0 * a0.y; acc0.z += d0 * a0.z; acc0.w += d0 * a0.w;
        acc1.x += d0 * a1.x; acc1.y += d0 * a1.y; acc1.z += d0 * a1.z; acc1.w += d0 * a1.w;
    }

    // Heavy-node path (never taken on this input; correctness fallback).
    if (cnt > STRIDE) {
        int novf = g_novf;
        if (novf > OVFCAP) novf = OVFCAP;
        for (int j2 = 0; j2 < novf; j2++) {
            int2 ov = g_ovf[j2];
            if (ov.x == node) {
                int2 ps = g_packed[ov.y];
                float ds = __int_as_float(ps.x);
                const float4* rr = &sW4[ps.y * WPITCH4 + f0];
                float4 a0 = rr[0], a1 = rr[1];
                acc0.x += ds * a0.x; acc0.y += ds * a0.y; acc0.z += ds * a0.z; acc0.w += ds * a0.w;
                acc1.x += ds * a1.x; acc1.y += ds * a1.y; acc1.z += ds * a1.z; acc1.w += ds * a1.w;
            }
        }
    }

    int col0 = sub * 8;
    float res = 0.f;
    res += tanha(acc0.x * dinv + sb[col0 + 0]) * so[col0 + 0];
    res += tanha(acc0.y * dinv + sb[col0 + 1]) * so[col0 + 1];
    res += tanha(acc0.z * dinv + sb[col0 + 2]) * so[col0 + 2];
    res += tanha(acc0.w * dinv + sb[col0 + 3]) * so[col0 + 3];
    res += tanha(acc1.x * dinv + sb[col0 + 4]) * so[col0 + 4];
    res += tanha(acc1.y * dinv + sb[col0 + 5]) * so[col0 + 5];
    res += tanha(acc1.z * dinv + sb[col0 + 6]) * so[col0 + 6];
    res += tanha(acc1.w * dinv + sb[col0 + 7]) * so[col0 + 7];

    // reduce across the 4 lanes of this node
    res += __shfl_xor_sync(0xffffffffu, res, 1);
    res += __shfl_xor_sync(0xffffffffu, res, 2);
    if (sub == 0) atomicAdd(&out[batch[node]], res);
}

// ---------------------------------------------------------------------------
// Launch
// Inputs: 0:x[N] i32, 1:edge_index[2E] i32, 2:batch[N] i32,
//         3:W[65*32] f32, 4:b_conv[32] f32, 5:W_out[32] f32, 6:b_out[1] f32
// Output: out[G] f32
// ---------------------------------------------------------------------------
extern "C" void kernel_launch(void* const* d_in, const int* in_sizes, int n_in,
                              void* d_out, int out_size) {
    const int*   x     = (const int*)d_in[0];
    const int*   eidx  = (const int*)d_in[1];
    const int*   batch = (const int*)d_in[2];
    const float* W     = (const float*)d_in[3];
    const float* bconv = (const float*)d_in[4];
    const float* Wout  = (const float*)d_in[5];
    const float* bout  = (const float*)d_in[6];
    float* out = (float*)d_out;

    int N = in_sizes[0];
    int E = in_sizes[1] / 2;
    int G = out_size;

    const int* src = eidx;
    const int* dst = eidx + E;

    int initN = N > G ? N : G;
    int nbE4  = ((E + 3) / 4 + TB - 1) / TB;
    int nbN   = (N + TB - 1) / TB;
    int nbN4  = (int)(((size_t)N * 4 + TB - 1) / TB);

    k_init   <<<(initN + TB - 1) / TB, TB>>>(out, bout, N, G);
    k_degfill<<<nbE4, TB>>>(src, dst, E);
    k_pack   <<<nbN, TB>>>(x, N);
    k_aggpool<<<nbN4, TB>>>(batch, W, bconv, Wout, out, N);
}